// round 5
// baseline (speedup 1.0000x reference)
#include <cuda_runtime.h>
#include <cuda_bf16.h>

// USER_NUM=1000, SKILL_NUM=256, K_HIDDEN=128, N_ITEMS=4096, SEQ_LEN=8192
// out[l, k] = sum_{s : Q[items[l], s] != 0} E[user, s, k]
//
// Single fused kernel (one launch -> one T_ovh). One warp processes TWO
// positions; their gather streams interleave for 8 independent LDG.128 in
// flight. Q/E stay L2/L1-hot across graph replays.

#define SEQ_LEN   8192
#define N_ITEMS   4096
#define SKILLS    256
#define K_HIDDEN  128
#define MAX_NNZ   96        // binomial(256,0.1): mean 25.6, std 4.8
#define WARPS_PER_CTA 8
#define HALF      (SEQ_LEN / 2)   // 4096 warps total

__global__ void __launch_bounds__(WARPS_PER_CTA * 32)
item_emb_fused2(const int* __restrict__ user_p,
                const float* __restrict__ Q,     // [N_ITEMS, SKILLS]
                const int* __restrict__ items,   // [SEQ_LEN]
                const float* __restrict__ emb,   // [USER_NUM, SKILLS, K_HIDDEN]
                float4* __restrict__ out4)       // [SEQ_LEN * 32]
{
    __shared__ int sA[WARPS_PER_CTA][MAX_NNZ];
    __shared__ int sB[WARPS_PER_CTA][MAX_NNZ];

    const int tid  = threadIdx.x;
    const int w    = tid >> 5;
    const int lane = tid & 31;
    const int wid  = blockIdx.x * WARPS_PER_CTA + w;   // 0 .. HALF-1
    const int posA = wid;
    const int posB = wid + HALF;

    const int user = user_p[0];
    const float4* __restrict__ E4 =
        reinterpret_cast<const float4*>(emb + (long long)user * SKILLS * K_HIDDEN) + lane;

    // Two item ids (independent loads)
    const int itemA = __ldg(&items[posA]);
    const int itemB = __ldg(&items[posB]);

    // Prefetch both Q rows: 4 independent LDG.128, coalesced
    const float4* __restrict__ qA =
        reinterpret_cast<const float4*>(Q + (long long)itemA * SKILLS);
    const float4* __restrict__ qB =
        reinterpret_cast<const float4*>(Q + (long long)itemB * SKILLS);
    const float4 a0 = qA[lane], a1 = qA[lane + 32];
    const float4 b0 = qB[lane], b1 = qB[lane + 32];

    // Ballot-compact nonzero skill indices for both positions
    const unsigned lt_mask = (1u << lane) - 1u;
    int svls[8] = {4*lane, 4*lane+1, 4*lane+2, 4*lane+3,
                   128+4*lane, 128+4*lane+1, 128+4*lane+2, 128+4*lane+3};

    float vA[8] = {a0.x, a0.y, a0.z, a0.w, a1.x, a1.y, a1.z, a1.w};
    int nA = 0;
    #pragma unroll
    for (int t = 0; t < 8; t++) {
        const bool nz = (vA[t] != 0.0f);
        const unsigned m = __ballot_sync(0xffffffffu, nz);
        if (nz) {
            const int p = nA + __popc(m & lt_mask);
            if (p < MAX_NNZ) sA[w][p] = svls[t];
        }
        nA += __popc(m);
    }
    float vB[8] = {b0.x, b0.y, b0.z, b0.w, b1.x, b1.y, b1.z, b1.w};
    int nB = 0;
    #pragma unroll
    for (int t = 0; t < 8; t++) {
        const bool nz = (vB[t] != 0.0f);
        const unsigned m = __ballot_sync(0xffffffffu, nz);
        if (nz) {
            const int p = nB + __popc(m & lt_mask);
            if (p < MAX_NNZ) sB[w][p] = svls[t];
        }
        nB += __popc(m);
    }
    __syncwarp();
    nA = min(nA, MAX_NNZ);
    nB = min(nB, MAX_NNZ);

    // ---- Interleaved gather-accumulate: 8 LDG.128 in flight per iteration ----
    float4 accA = make_float4(0.f, 0.f, 0.f, 0.f);
    float4 accB = make_float4(0.f, 0.f, 0.f, 0.f);

    const int nmin = min(nA, nB);
    int j = 0;
    for (; j + 4 <= nmin; j += 4) {
        const int sa0 = sA[w][j+0], sa1 = sA[w][j+1], sa2 = sA[w][j+2], sa3 = sA[w][j+3];
        const int sb0 = sB[w][j+0], sb1 = sB[w][j+1], sb2 = sB[w][j+2], sb3 = sB[w][j+3];
        const float4 ea0 = E4[sa0 * 32];
        const float4 eb0 = E4[sb0 * 32];
        const float4 ea1 = E4[sa1 * 32];
        const float4 eb1 = E4[sb1 * 32];
        const float4 ea2 = E4[sa2 * 32];
        const float4 eb2 = E4[sb2 * 32];
        const float4 ea3 = E4[sa3 * 32];
        const float4 eb3 = E4[sb3 * 32];
        accA.x += (ea0.x + ea1.x) + (ea2.x + ea3.x);
        accA.y += (ea0.y + ea1.y) + (ea2.y + ea3.y);
        accA.z += (ea0.z + ea1.z) + (ea2.z + ea3.z);
        accA.w += (ea0.w + ea1.w) + (ea2.w + ea3.w);
        accB.x += (eb0.x + eb1.x) + (eb2.x + eb3.x);
        accB.y += (eb0.y + eb1.y) + (eb2.y + eb3.y);
        accB.z += (eb0.z + eb1.z) + (eb2.z + eb3.z);
        accB.w += (eb0.w + eb1.w) + (eb2.w + eb3.w);
    }
    // Tail A (4-wide then scalar)
    int ja = j;
    for (; ja + 4 <= nA; ja += 4) {
        const int s0 = sA[w][ja+0], s1 = sA[w][ja+1], s2 = sA[w][ja+2], s3 = sA[w][ja+3];
        const float4 e0 = E4[s0 * 32];
        const float4 e1 = E4[s1 * 32];
        const float4 e2 = E4[s2 * 32];
        const float4 e3 = E4[s3 * 32];
        accA.x += (e0.x + e1.x) + (e2.x + e3.x);
        accA.y += (e0.y + e1.y) + (e2.y + e3.y);
        accA.z += (e0.z + e1.z) + (e2.z + e3.z);
        accA.w += (e0.w + e1.w) + (e2.w + e3.w);
    }
    for (; ja < nA; ja++) {
        const float4 e = E4[sA[w][ja] * 32];
        accA.x += e.x; accA.y += e.y; accA.z += e.z; accA.w += e.w;
    }
    // Tail B
    int jb = j;
    for (; jb + 4 <= nB; jb += 4) {
        const int s0 = sB[w][jb+0], s1 = sB[w][jb+1], s2 = sB[w][jb+2], s3 = sB[w][jb+3];
        const float4 e0 = E4[s0 * 32];
        const float4 e1 = E4[s1 * 32];
        const float4 e2 = E4[s2 * 32];
        const float4 e3 = E4[s3 * 32];
        accB.x += (e0.x + e1.x) + (e2.x + e3.x);
        accB.y += (e0.y + e1.y) + (e2.y + e3.y);
        accB.z += (e0.z + e1.z) + (e2.z + e3.z);
        accB.w += (e0.w + e1.w) + (e2.w + e3.w);
    }
    for (; jb < nB; jb++) {
        const float4 e = E4[sB[w][jb] * 32];
        accB.x += e.x; accB.y += e.y; accB.z += e.z; accB.w += e.w;
    }

    out4[posA * 32 + lane] = accA;
    out4[posB * 32 + lane] = accB;
}

extern "C" void kernel_launch(void* const* d_in, const int* in_sizes, int n_in,
                              void* d_out, int out_size)
{
    const int*   user  = nullptr;
    const float* Q     = nullptr;
    const int*   items = nullptr;
    const float* emb   = nullptr;

    for (int i = 0; i < n_in; i++) {
        switch (in_sizes[i]) {
            case 1:                        user  = (const int*)  d_in[i]; break;
            case N_ITEMS * SKILLS:         Q     = (const float*)d_in[i]; break;
            case SEQ_LEN:                  items = (const int*)  d_in[i]; break;
            case 1000 * SKILLS * K_HIDDEN: emb   = (const float*)d_in[i]; break;
            default: break;
        }
    }
    if (!user)  user  = (const int*)  d_in[0];
    if (!Q)     Q     = (const float*)d_in[1];
    if (!items) items = (const int*)  d_in[2];
    if (!emb)   emb   = (const float*)d_in[3];

    // One warp per 2 positions: 4096 warps -> 512 CTAs of 256 threads
    item_emb_fused2<<<HALF / WARPS_PER_CTA, WARPS_PER_CTA * 32>>>(
        user, Q, items, emb, (float4*)d_out);
}

// round 11
// speedup vs baseline: 1.1458x; 1.1458x over previous
#include <cuda_runtime.h>
#include <cuda_bf16.h>

// USER_NUM=1000, SKILL_NUM=256, K_HIDDEN=128, N_ITEMS=4096, SEQ_LEN=8192
// out[l, k] = sum_{s : Q[items[l], s] != 0} E[user, s, k]
//
// Two-phase, split-K phase A:
//   Phase A: two warps per item (skills 0-127 / 128-255) -> partial sums in
//            g_partial[half][item]; ~13 gathers per warp, all in flight.
//   Phase B: out[l] = P0[items[l]] + P1[items[l]]  (L2-resident combine)

#define SEQ_LEN   8192
#define N_ITEMS   4096
#define SKILLS    256
#define K_HIDDEN  128
#define NNZ_CAP   64          // binomial(128,0.1): mean 12.8, std 3.4
#define WPC_A     8
#define THR_B     256

// Partial sums: 2 x 4096 x 32 float4 = 4 MB static device scratch (no alloc)
__device__ float4 g_partial[2 * N_ITEMS * (K_HIDDEN / 4)];

// ---------------- Phase A ----------------
__global__ void __launch_bounds__(WPC_A * 32)
ksplit_rowsum(const int* __restrict__ user_p,
              const float* __restrict__ Q,     // [N_ITEMS, SKILLS]
              const float* __restrict__ emb)   // [USER_NUM, SKILLS, K_HIDDEN]
{
    __shared__ int sidx[WPC_A][NNZ_CAP];

    const int tid  = threadIdx.x;
    const int w    = tid >> 5;
    const int lane = tid & 31;
    const int wid  = blockIdx.x * WPC_A + w;    // 0 .. 2*N_ITEMS-1
    const int item = wid >> 1;
    const int half = wid & 1;

    const int user = user_p[0];
    const float4* __restrict__ E4 =
        reinterpret_cast<const float4*>(emb + (long long)user * SKILLS * K_HIDDEN) + lane;

    // This half's 128 skills: one coalesced float4 per lane
    const float4 v = reinterpret_cast<const float4*>(
        Q + (long long)item * SKILLS + half * 128)[lane];

    // Ballot-compact nonzero skill ids
    const int s_base = half * 128 + 4 * lane;
    const float vals[4] = {v.x, v.y, v.z, v.w};
    const unsigned lt_mask = (1u << lane) - 1u;
    int nnz = 0;
    #pragma unroll
    for (int t = 0; t < 4; t++) {
        const bool nz = (vals[t] != 0.0f);
        const unsigned m = __ballot_sync(0xffffffffu, nz);
        if (nz) {
            const int p = nnz + __popc(m & lt_mask);
            if (p < NNZ_CAP) sidx[w][p] = s_base + t;
        }
        nnz += __popc(m);
    }
    __syncwarp();
    nnz = min(nnz, NNZ_CAP);

    // Gather-accumulate: 8 loads in flight, 2 accumulators; typical nnz ~13
    float4 a0 = make_float4(0.f, 0.f, 0.f, 0.f);
    float4 a1 = make_float4(0.f, 0.f, 0.f, 0.f);
    int j = 0;
    for (; j + 8 <= nnz; j += 8) {
        int s[8];
        #pragma unroll
        for (int t = 0; t < 8; t++) s[t] = sidx[w][j + t];
        float4 e[8];
        #pragma unroll
        for (int t = 0; t < 8; t++) e[t] = E4[s[t] * 32];
        #pragma unroll
        for (int t = 0; t < 4; t++) {
            a0.x += e[t].x;   a0.y += e[t].y;   a0.z += e[t].z;   a0.w += e[t].w;
            a1.x += e[t+4].x; a1.y += e[t+4].y; a1.z += e[t+4].z; a1.w += e[t+4].w;
        }
    }
    if (j + 4 <= nnz) {
        const int s0 = sidx[w][j+0], s1 = sidx[w][j+1];
        const int s2 = sidx[w][j+2], s3 = sidx[w][j+3];
        const float4 e0 = E4[s0 * 32];
        const float4 e1 = E4[s1 * 32];
        const float4 e2 = E4[s2 * 32];
        const float4 e3 = E4[s3 * 32];
        a0.x += (e0.x + e1.x) + (e2.x + e3.x);
        a0.y += (e0.y + e1.y) + (e2.y + e3.y);
        a0.z += (e0.z + e1.z) + (e2.z + e3.z);
        a0.w += (e0.w + e1.w) + (e2.w + e3.w);
        j += 4;
    }
    for (; j < nnz; j++) {
        const float4 e = E4[sidx[w][j] * 32];
        a1.x += e.x; a1.y += e.y; a1.z += e.z; a1.w += e.w;
    }

    float4 acc;
    acc.x = a0.x + a1.x; acc.y = a0.y + a1.y;
    acc.z = a0.z + a1.z; acc.w = a0.w + a1.w;
    g_partial[(half * N_ITEMS + item) * 32 + lane] = acc;
}

// ---------------- Phase B ----------------
__global__ void __launch_bounds__(THR_B)
kcombine(const int* __restrict__ items,   // [SEQ_LEN]
         float4* __restrict__ out4)       // [SEQ_LEN * 32]
{
    const int STRIDE = SEQ_LEN * (K_HIDDEN / 4) / 2;   // 131072
    const int t = blockIdx.x * THR_B + threadIdx.x;

    const int g0 = t;
    const int g1 = t + STRIDE;
    const int it0 = __ldg(&items[g0 >> 5]);
    const int it1 = __ldg(&items[g1 >> 5]);
    const int q0 = g0 & 31;
    const int q1 = g1 & 31;

    // 4 independent LDG.128 from L2-resident scratch
    const float4 r00 = g_partial[it0 * 32 + q0];
    const float4 r10 = g_partial[(N_ITEMS + it0) * 32 + q0];
    const float4 r01 = g_partial[it1 * 32 + q1];
    const float4 r11 = g_partial[(N_ITEMS + it1) * 32 + q1];

    float4 o0, o1;
    o0.x = r00.x + r10.x; o0.y = r00.y + r10.y;
    o0.z = r00.z + r10.z; o0.w = r00.w + r10.w;
    o1.x = r01.x + r11.x; o1.y = r01.y + r11.y;
    o1.z = r01.z + r11.z; o1.w = r01.w + r11.w;

    out4[g0] = o0;
    out4[g1] = o1;
}

extern "C" void kernel_launch(void* const* d_in, const int* in_sizes, int n_in,
                              void* d_out, int out_size)
{
    const int*   user  = nullptr;
    const float* Q     = nullptr;
    const int*   items = nullptr;
    const float* emb   = nullptr;

    for (int i = 0; i < n_in; i++) {
        switch (in_sizes[i]) {
            case 1:                        user  = (const int*)  d_in[i]; break;
            case N_ITEMS * SKILLS:         Q     = (const float*)d_in[i]; break;
            case SEQ_LEN:                  items = (const int*)  d_in[i]; break;
            case 1000 * SKILLS * K_HIDDEN: emb   = (const float*)d_in[i]; break;
            default: break;
        }
    }
    if (!user)  user  = (const int*)  d_in[0];
    if (!Q)     Q     = (const float*)d_in[1];
    if (!items) items = (const int*)  d_in[2];
    if (!emb)   emb   = (const float*)d_in[3];

    // Phase A: 2 warps/item -> 8192 warps -> 1024 CTAs x 256 threads
    ksplit_rowsum<<<(2 * N_ITEMS) / WPC_A, WPC_A * 32>>>(user, Q, emb);

    // Phase B: 2 float4s/thread -> 512 CTAs x 256 threads
    kcombine<<<(SEQ_LEN * (K_HIDDEN / 4) / 2) / THR_B, THR_B>>>(items, (float4*)d_out);
}